// round 2
// baseline (speedup 1.0000x reference)
#include <cuda_runtime.h>

#define Bv 4
#define Tv 256
#define Ev 512
#define Hv 8
#define Sv 64

// scratch (allocation-free rule: __device__ globals)
__device__ float g_q[Bv*Tv*Ev];
__device__ float g_k[Bv*Tv*Ev];
__device__ float g_v[Bv*Tv*Ev];
__device__ float g_scc[Bv*Hv*Tv*Tv];   // [b][n][i][j]
__device__ float g_vec[Bv*Tv*Ev];

// ---------------------------------------------------------------------------
// K1: per-token q/k/v projections.  q[b,t,n,o] = sum_d x[b,t,n*64+d]*W[o,d]
// ---------------------------------------------------------------------------
__global__ void __launch_bounds__(256) qkv_kernel(const float* __restrict__ x,
                                                  const float* __restrict__ Wq,
                                                  const float* __restrict__ Wk,
                                                  const float* __restrict__ Wv)
{
    __shared__ float Ws[64][65];
    __shared__ float xs[Ev];
    const int bt  = blockIdx.x;
    const int tid = threadIdx.x;

    xs[tid]       = x[(size_t)bt*Ev + tid];
    xs[tid + 256] = x[(size_t)bt*Ev + tid + 256];

    const float* Wlist[3] = {Wq, Wk, Wv};
    float*       Olist[3] = {g_q, g_k, g_v};

    #pragma unroll
    for (int w = 0; w < 3; w++) {
        __syncthreads();
        const float* W = Wlist[w];
        for (int idx = tid; idx < 64*64; idx += 256)
            Ws[idx >> 6][idx & 63] = W[idx];
        __syncthreads();

        const int e0 = 2 * tid;
        const int n  = e0 >> 6;
        const int o0 = e0 & 63;
        const float* xr = &xs[n * 64];
        float a0 = 0.f, a1 = 0.f;
        #pragma unroll
        for (int d = 0; d < 64; d++) {
            const float xv = xr[d];
            a0 = fmaf(xv, Ws[o0][d],     a0);
            a1 = fmaf(xv, Ws[o0 + 1][d], a1);
        }
        Olist[w][(size_t)bt*Ev + e0]     = a0;
        Olist[w][(size_t)bt*Ev + e0 + 1] = a1;
    }
}

// ---------------------------------------------------------------------------
// K2: content-content scores  scc[b][n][i][j] = sum_d q[b,i,n,d]*k[b,j,n,d]
// ---------------------------------------------------------------------------
__global__ void __launch_bounds__(256) scc_kernel()
{
    __shared__ float qs[64][65];
    __shared__ float ks[64][65];
    const int it = blockIdx.x * 64;
    const int jt = blockIdx.y * 64;
    const int b  = blockIdx.z >> 3;
    const int n  = blockIdx.z & 7;
    const int tid = threadIdx.x;

    for (int idx = tid; idx < 4096; idx += 256) {
        const int r = idx >> 6, d = idx & 63;
        qs[r][d] = g_q[(((size_t)b*Tv + it + r)*Hv + n)*Sv + d];
        ks[r][d] = g_k[(((size_t)b*Tv + jt + r)*Hv + n)*Sv + d];
    }
    __syncthreads();

    const int ty = tid >> 4, tx = tid & 15;
    float acc[4][4] = {};
    #pragma unroll 8
    for (int d = 0; d < 64; d++) {
        float a[4], c[4];
        #pragma unroll
        for (int r = 0; r < 4; r++) a[r] = qs[ty*4 + r][d];
        #pragma unroll
        for (int cc = 0; cc < 4; cc++) c[cc] = ks[tx*4 + cc][d];
        #pragma unroll
        for (int r = 0; r < 4; r++)
            #pragma unroll
            for (int cc = 0; cc < 4; cc++)
                acc[r][cc] = fmaf(a[r], c[cc], acc[r][cc]);
    }

    #pragma unroll
    for (int r = 0; r < 4; r++)
        #pragma unroll
        for (int cc = 0; cc < 4; cc++)
            g_scc[(((size_t)b*Hv + n)*Tv + it + ty*4 + r)*Tv + jt + tx*4 + cc] = acc[r][cc];
}

// ---------------------------------------------------------------------------
// K3: streaming attention. One CTA per (b,i); warp n = head n.
// float4 loads; half-warp (16 lanes) per j row (64 floats = 16 x float4).
// ---------------------------------------------------------------------------
__global__ void __launch_bounds__(256) attn_kernel(const float* __restrict__ ek,
                                                   const float* __restrict__ ev,
                                                   const int*   __restrict__ mask)
{
    __shared__ float sc[Hv][Tv];     // scores -> probs

    const int bi   = blockIdx.x;
    const int b    = bi >> 8;
    const int i    = bi & 255;
    const int tid  = threadIdx.x;
    const int warp = tid >> 5;       // head
    const int lane = tid & 31;
    const int half = lane >> 4;      // 0 or 1
    const int l    = lane & 15;      // lane within half-warp

    // preload content-content scores: sc[n][j]
    #pragma unroll
    for (int t = 0; t < 8; t++)
        sc[t][tid] = g_scc[(((size_t)b*Hv + t)*Tv + i)*Tv + tid];

    // q slice for this head, float4 per lane (same for both halves)
    const float4 q4 = ((const float4*)g_q)[(size_t)bi*128 + warp*16 + l];
    __syncthreads();

    // ---- Pass A: stream ek; each half-warp reduces one j row ----
    const float4* ekp = (const float4*)ek + (size_t)bi*Tv*128 + warp*16 + l;
    for (int j0 = 0; j0 < Tv; j0 += 8) {
        float4 r[4];
        #pragma unroll
        for (int u = 0; u < 4; u++)
            r[u] = ekp[(size_t)(j0 + 2*u + half) * 128];
        #pragma unroll
        for (int u = 0; u < 4; u++) {
            float p = fmaf(r[u].x, q4.x,
                      fmaf(r[u].y, q4.y,
                      fmaf(r[u].z, q4.z, r[u].w * q4.w)));
            p += __shfl_xor_sync(0xffffffffu, p, 8);
            p += __shfl_xor_sync(0xffffffffu, p, 4);
            p += __shfl_xor_sync(0xffffffffu, p, 2);
            p += __shfl_xor_sync(0xffffffffu, p, 1);
            if (l == 0) sc[warp][j0 + 2*u + half] += p;
        }
    }
    __syncwarp();

    // ---- softmax per head (warp-local over 256 j) ----
    const float scale = 0.125f;   // 1/sqrt(64)
    const int* mrow = mask + (size_t)bi * Tv;
    float vbuf[8];
    float mx = -1e30f;
    #pragma unroll
    for (int t = 0; t < 8; t++) {
        const int j = lane + 32*t;
        float s = sc[warp][j];
        s = (mrow[j] == 0) ? -1e9f : s * scale;
        vbuf[t] = s;
        mx = fmaxf(mx, s);
    }
    mx = fmaxf(mx, __shfl_xor_sync(0xffffffffu, mx, 16));
    mx = fmaxf(mx, __shfl_xor_sync(0xffffffffu, mx, 8));
    mx = fmaxf(mx, __shfl_xor_sync(0xffffffffu, mx, 4));
    mx = fmaxf(mx, __shfl_xor_sync(0xffffffffu, mx, 2));
    mx = fmaxf(mx, __shfl_xor_sync(0xffffffffu, mx, 1));
    float sum = 0.f;
    #pragma unroll
    for (int t = 0; t < 8; t++) {
        const float e = expf(vbuf[t] - mx);
        vbuf[t] = e;
        sum += e;
    }
    sum += __shfl_xor_sync(0xffffffffu, sum, 16);
    sum += __shfl_xor_sync(0xffffffffu, sum, 8);
    sum += __shfl_xor_sync(0xffffffffu, sum, 4);
    sum += __shfl_xor_sync(0xffffffffu, sum, 2);
    sum += __shfl_xor_sync(0xffffffffu, sum, 1);
    const float inv = 1.f / sum;
    #pragma unroll
    for (int t = 0; t < 8; t++)
        sc[warp][lane + 32*t] = vbuf[t] * inv;
    __syncwarp();

    // ---- Pass B: stream ev + L2-hit v, weighted accumulate (float4) ----
    const float4* evp = (const float4*)ev  + (size_t)bi*Tv*128 + warp*16 + l;
    const float4* vp  = (const float4*)g_v + (size_t)b *Tv*128 + warp*16 + l;
    float4 acc = make_float4(0.f, 0.f, 0.f, 0.f);
    for (int j0 = 0; j0 < Tv; j0 += 8) {
        float4 re[4], rv[4];
        #pragma unroll
        for (int u = 0; u < 4; u++) {
            const size_t off = (size_t)(j0 + 2*u + half) * 128;
            re[u] = evp[off];
            rv[u] = vp[off];
        }
        #pragma unroll
        for (int u = 0; u < 4; u++) {
            const float p = sc[warp][j0 + 2*u + half];
            acc.x = fmaf(p, re[u].x + rv[u].x, acc.x);
            acc.y = fmaf(p, re[u].y + rv[u].y, acc.y);
            acc.z = fmaf(p, re[u].z + rv[u].z, acc.z);
            acc.w = fmaf(p, re[u].w + rv[u].w, acc.w);
        }
    }
    // combine the two half-warp partial sums (each half covered j of one parity)
    acc.x += __shfl_xor_sync(0xffffffffu, acc.x, 16);
    acc.y += __shfl_xor_sync(0xffffffffu, acc.y, 16);
    acc.z += __shfl_xor_sync(0xffffffffu, acc.z, 16);
    acc.w += __shfl_xor_sync(0xffffffffu, acc.w, 16);
    if (half == 0)
        ((float4*)g_vec)[(size_t)bi*128 + warp*16 + l] = acc;
}

// ---------------------------------------------------------------------------
// K4: out = vec @ Wu^T + bu   ([1024,512] x [512,512]^T), 64x64 tiles
// K-major smem tiles with 16B-aligned rows (stride 68) -> LDS.128 inner loop.
// ---------------------------------------------------------------------------
__global__ void __launch_bounds__(256) proj_kernel(const float* __restrict__ Wu,
                                                   const float* __restrict__ bu,
                                                   float* __restrict__ out)
{
    __shared__ float As[64][68];   // [k][r] vec tile
    __shared__ float Bs[64][68];   // [k][c] Wu tile
    const int r0  = blockIdx.x * 64;
    const int c0  = blockIdx.y * 64;
    const int tid = threadIdx.x;
    const int ty  = tid >> 4, tx = tid & 15;

    float acc[4][4] = {};
    for (int k0 = 0; k0 < Ev; k0 += 64) {
        __syncthreads();
        // coalesced gmem reads (contiguous k), transposed smem writes
        for (int idx = tid; idx < 4096; idx += 256) {
            const int r = idx >> 6, k = idx & 63;
            As[k][r] = g_vec[(size_t)(r0 + r)*Ev + k0 + k];
            Bs[k][r] = Wu[(size_t)(c0 + r)*Ev + k0 + k];
        }
        __syncthreads();
        #pragma unroll 4
        for (int k = 0; k < 64; k++) {
            const float4 a4 = *(const float4*)&As[k][ty*4];
            const float4 c4 = *(const float4*)&Bs[k][tx*4];
            const float a[4] = {a4.x, a4.y, a4.z, a4.w};
            const float c[4] = {c4.x, c4.y, c4.z, c4.w};
            #pragma unroll
            for (int ry = 0; ry < 4; ry++)
                #pragma unroll
                for (int cx = 0; cx < 4; cx++)
                    acc[ry][cx] = fmaf(a[ry], c[cx], acc[ry][cx]);
        }
    }

    #pragma unroll
    for (int ry = 0; ry < 4; ry++)
        #pragma unroll
        for (int cx = 0; cx < 4; cx++)
            out[(size_t)(r0 + ty*4 + ry)*Ev + c0 + tx*4 + cx] =
                acc[ry][cx] + bu[c0 + tx*4 + cx];
}

// ---------------------------------------------------------------------------
extern "C" void kernel_launch(void* const* d_in, const int* in_sizes, int n_in,
                              void* d_out, int out_size)
{
    const float* x   = (const float*)d_in[0];
    const float* rk  = (const float*)d_in[1];
    const float* rv  = (const float*)d_in[2];
    const int*   msk = (const int*)  d_in[3];
    const float* Wq  = (const float*)d_in[4];
    const float* Wk  = (const float*)d_in[5];
    const float* Wv  = (const float*)d_in[6];
    const float* Wu  = (const float*)d_in[7];
    const float* bu  = (const float*)d_in[8];
    float* out = (float*)d_out;

    qkv_kernel<<<Bv*Tv, 256>>>(x, Wq, Wk, Wv);
    scc_kernel<<<dim3(4, 4, Bv*Hv), 256>>>();
    attn_kernel<<<Bv*Tv, 256>>>(rk, rv, msk);
    proj_kernel<<<dim3(16, 8), 256>>>(Wu, bu, out);
}

// round 3
// speedup vs baseline: 1.0026x; 1.0026x over previous
#include <cuda_runtime.h>

#define Bv 4
#define Tv 256
#define Ev 512
#define Hv 8
#define Sv 64

// scratch (allocation-free rule: __device__ globals)
__device__ float g_q[Bv*Tv*Ev];
__device__ float g_k[Bv*Tv*Ev];
__device__ float g_v[Bv*Tv*Ev];
__device__ float g_scc[Bv*Hv*Tv*Tv];   // [b][n][i][j]
__device__ float g_vec[Bv*Tv*Ev];

// ---------------------------------------------------------------------------
// K1: per-token q/k/v projections.  q[b,t,n,o] = sum_d x[b,t,n*64+d]*W[o,d]
// ---------------------------------------------------------------------------
__global__ void __launch_bounds__(256) qkv_kernel(const float* __restrict__ x,
                                                  const float* __restrict__ Wq,
                                                  const float* __restrict__ Wk,
                                                  const float* __restrict__ Wv)
{
    __shared__ float Ws[64][65];
    __shared__ float xs[Ev];
    const int bt  = blockIdx.x;
    const int tid = threadIdx.x;

    xs[tid]       = x[(size_t)bt*Ev + tid];
    xs[tid + 256] = x[(size_t)bt*Ev + tid + 256];

    const float* Wlist[3] = {Wq, Wk, Wv};
    float*       Olist[3] = {g_q, g_k, g_v};

    #pragma unroll
    for (int w = 0; w < 3; w++) {
        __syncthreads();
        const float* W = Wlist[w];
        for (int idx = tid; idx < 64*64; idx += 256)
            Ws[idx >> 6][idx & 63] = W[idx];
        __syncthreads();

        const int e0 = 2 * tid;
        const int n  = e0 >> 6;
        const int o0 = e0 & 63;
        const float* xr = &xs[n * 64];
        float a0 = 0.f, a1 = 0.f;
        #pragma unroll
        for (int d = 0; d < 64; d++) {
            const float xv = xr[d];
            a0 = fmaf(xv, Ws[o0][d],     a0);
            a1 = fmaf(xv, Ws[o0 + 1][d], a1);
        }
        Olist[w][(size_t)bt*Ev + e0]     = a0;
        Olist[w][(size_t)bt*Ev + e0 + 1] = a1;
    }
}

// ---------------------------------------------------------------------------
// K2: content-content scores  scc[b][n][i][j] = sum_d q[b,i,n,d]*k[b,j,n,d]
// ---------------------------------------------------------------------------
__global__ void __launch_bounds__(256) scc_kernel()
{
    __shared__ float qs[64][65];
    __shared__ float ks[64][65];
    const int it = blockIdx.x * 64;
    const int jt = blockIdx.y * 64;
    const int b  = blockIdx.z >> 3;
    const int n  = blockIdx.z & 7;
    const int tid = threadIdx.x;

    for (int idx = tid; idx < 4096; idx += 256) {
        const int r = idx >> 6, d = idx & 63;
        qs[r][d] = g_q[(((size_t)b*Tv + it + r)*Hv + n)*Sv + d];
        ks[r][d] = g_k[(((size_t)b*Tv + jt + r)*Hv + n)*Sv + d];
    }
    __syncthreads();

    const int ty = tid >> 4, tx = tid & 15;
    float acc[4][4] = {};
    #pragma unroll 8
    for (int d = 0; d < 64; d++) {
        float a[4], c[4];
        #pragma unroll
        for (int r = 0; r < 4; r++) a[r] = qs[ty*4 + r][d];
        #pragma unroll
        for (int cc = 0; cc < 4; cc++) c[cc] = ks[tx*4 + cc][d];
        #pragma unroll
        for (int r = 0; r < 4; r++)
            #pragma unroll
            for (int cc = 0; cc < 4; cc++)
                acc[r][cc] = fmaf(a[r], c[cc], acc[r][cc]);
    }

    #pragma unroll
    for (int r = 0; r < 4; r++)
        #pragma unroll
        for (int cc = 0; cc < 4; cc++)
            g_scc[(((size_t)b*Hv + n)*Tv + it + ty*4 + r)*Tv + jt + tx*4 + cc] = acc[r][cc];
}

// ---------------------------------------------------------------------------
// K3: streaming attention. One CTA per (b,i); warp n = head n.
// ek/ev loaded with __ldcs (evict-first) so L2 keeps v resident.
// ---------------------------------------------------------------------------
__global__ void __launch_bounds__(256) attn_kernel(const float* __restrict__ ek,
                                                   const float* __restrict__ ev,
                                                   const int*   __restrict__ mask)
{
    __shared__ float sc[Hv][Tv];     // scores -> probs

    const int bi   = blockIdx.x;
    const int b    = bi >> 8;
    const int i    = bi & 255;
    const int tid  = threadIdx.x;
    const int warp = tid >> 5;       // head
    const int lane = tid & 31;
    const int half = lane >> 4;      // 0 or 1
    const int l    = lane & 15;      // lane within half-warp

    // preload content-content scores: sc[n][j]
    #pragma unroll
    for (int t = 0; t < 8; t++)
        sc[t][tid] = g_scc[(((size_t)b*Hv + t)*Tv + i)*Tv + tid];

    // q slice for this head, float4 per lane (same for both halves)
    const float4 q4 = ((const float4*)g_q)[(size_t)bi*128 + warp*16 + l];
    __syncthreads();

    // ---- Pass A: stream ek; each half-warp reduces one j row ----
    const float4* ekp = (const float4*)ek + (size_t)bi*Tv*128 + warp*16 + l;
    for (int j0 = 0; j0 < Tv; j0 += 8) {
        float4 r[4];
        #pragma unroll
        for (int u = 0; u < 4; u++)
            r[u] = __ldcs(&ekp[(size_t)(j0 + 2*u + half) * 128]);
        #pragma unroll
        for (int u = 0; u < 4; u++) {
            float p = fmaf(r[u].x, q4.x,
                      fmaf(r[u].y, q4.y,
                      fmaf(r[u].z, q4.z, r[u].w * q4.w)));
            p += __shfl_xor_sync(0xffffffffu, p, 8);
            p += __shfl_xor_sync(0xffffffffu, p, 4);
            p += __shfl_xor_sync(0xffffffffu, p, 2);
            p += __shfl_xor_sync(0xffffffffu, p, 1);
            if (l == 0) sc[warp][j0 + 2*u + half] += p;
        }
    }
    __syncwarp();

    // ---- softmax per head (warp-local over 256 j) ----
    const float scale = 0.125f;   // 1/sqrt(64)
    const int* mrow = mask + (size_t)bi * Tv;
    float vbuf[8];
    float mx = -1e30f;
    #pragma unroll
    for (int t = 0; t < 8; t++) {
        const int j = lane + 32*t;
        float s = sc[warp][j];
        s = (mrow[j] == 0) ? -1e9f : s * scale;
        vbuf[t] = s;
        mx = fmaxf(mx, s);
    }
    mx = fmaxf(mx, __shfl_xor_sync(0xffffffffu, mx, 16));
    mx = fmaxf(mx, __shfl_xor_sync(0xffffffffu, mx, 8));
    mx = fmaxf(mx, __shfl_xor_sync(0xffffffffu, mx, 4));
    mx = fmaxf(mx, __shfl_xor_sync(0xffffffffu, mx, 2));
    mx = fmaxf(mx, __shfl_xor_sync(0xffffffffu, mx, 1));
    float sum = 0.f;
    #pragma unroll
    for (int t = 0; t < 8; t++) {
        const float e = expf(vbuf[t] - mx);
        vbuf[t] = e;
        sum += e;
    }
    sum += __shfl_xor_sync(0xffffffffu, sum, 16);
    sum += __shfl_xor_sync(0xffffffffu, sum, 8);
    sum += __shfl_xor_sync(0xffffffffu, sum, 4);
    sum += __shfl_xor_sync(0xffffffffu, sum, 2);
    sum += __shfl_xor_sync(0xffffffffu, sum, 1);
    const float inv = 1.f / sum;
    #pragma unroll
    for (int t = 0; t < 8; t++)
        sc[warp][lane + 32*t] = vbuf[t] * inv;
    __syncwarp();

    // ---- Pass B: stream ev (__ldcs) + L2-resident v, weighted accumulate ----
    const float4* evp = (const float4*)ev  + (size_t)bi*Tv*128 + warp*16 + l;
    const float4* vp  = (const float4*)g_v + (size_t)b *Tv*128 + warp*16 + l;
    float4 acc = make_float4(0.f, 0.f, 0.f, 0.f);
    for (int j0 = 0; j0 < Tv; j0 += 8) {
        float4 re[4], rv[4];
        #pragma unroll
        for (int u = 0; u < 4; u++) {
            const size_t off = (size_t)(j0 + 2*u + half) * 128;
            re[u] = __ldcs(&evp[off]);
            rv[u] = vp[off];
        }
        #pragma unroll
        for (int u = 0; u < 4; u++) {
            const float p = sc[warp][j0 + 2*u + half];
            acc.x = fmaf(p, re[u].x + rv[u].x, acc.x);
            acc.y = fmaf(p, re[u].y + rv[u].y, acc.y);
            acc.z = fmaf(p, re[u].z + rv[u].z, acc.z);
            acc.w = fmaf(p, re[u].w + rv[u].w, acc.w);
        }
    }
    // combine the two half-warp partial sums (each half covered j of one parity)
    acc.x += __shfl_xor_sync(0xffffffffu, acc.x, 16);
    acc.y += __shfl_xor_sync(0xffffffffu, acc.y, 16);
    acc.z += __shfl_xor_sync(0xffffffffu, acc.z, 16);
    acc.w += __shfl_xor_sync(0xffffffffu, acc.w, 16);
    if (half == 0)
        ((float4*)g_vec)[(size_t)bi*128 + warp*16 + l] = acc;
}

// ---------------------------------------------------------------------------
// K4: out = vec @ Wu^T + bu.  BM=64, BN=32, 64 threads, TM=8 x TN=4.
// grid = (16,16) = 256 CTAs -> all 148 SMs busy, ~2 CTAs/SM overlap.
// K-major smem tiles -> LDS.128, FMA-bound inner loop.
// ---------------------------------------------------------------------------
__global__ void __launch_bounds__(64) proj_kernel(const float* __restrict__ Wu,
                                                  const float* __restrict__ bu,
                                                  float* __restrict__ out)
{
    __shared__ float As[64][68];   // [k][r]  (r0..r0+63)
    __shared__ float Bs[64][36];   // [k][c]  (c0..c0+31)
    const int r0  = blockIdx.x * 64;
    const int c0  = blockIdx.y * 32;
    const int tid = threadIdx.x;
    const int ty  = tid >> 3;       // 0..7  -> rows ty*8 .. ty*8+7
    const int tx  = tid & 7;        // 0..7  -> cols tx*4 .. tx*4+3

    float acc[8][4] = {};

    for (int k0 = 0; k0 < Ev; k0 += 64) {
        __syncthreads();
        // As: 64 rows x 64 k, vectorized gmem read, transposed smem store
        for (int ch = tid; ch < 1024; ch += 64) {        // 1024 float4 chunks
            const int r = ch >> 4, k = (ch & 15) * 4;
            const float4 v4 = *(const float4*)&g_vec[(size_t)(r0 + r)*Ev + k0 + k];
            As[k][r] = v4.x; As[k+1][r] = v4.y; As[k+2][r] = v4.z; As[k+3][r] = v4.w;
        }
        // Bs: 32 rows x 64 k
        for (int ch = tid; ch < 512; ch += 64) {
            const int c = ch >> 4, k = (ch & 15) * 4;
            const float4 v4 = *(const float4*)&Wu[(size_t)(c0 + c)*Ev + k0 + k];
            Bs[k][c] = v4.x; Bs[k+1][c] = v4.y; Bs[k+2][c] = v4.z; Bs[k+3][c] = v4.w;
        }
        __syncthreads();

        #pragma unroll 4
        for (int k = 0; k < 64; k++) {
            const float4 a0 = *(const float4*)&As[k][ty*8];
            const float4 a1 = *(const float4*)&As[k][ty*8 + 4];
            const float4 b4 = *(const float4*)&Bs[k][tx*4];
            const float a[8] = {a0.x, a0.y, a0.z, a0.w, a1.x, a1.y, a1.z, a1.w};
            const float c[4] = {b4.x, b4.y, b4.z, b4.w};
            #pragma unroll
            for (int ry = 0; ry < 8; ry++)
                #pragma unroll
                for (int cx = 0; cx < 4; cx++)
                    acc[ry][cx] = fmaf(a[ry], c[cx], acc[ry][cx]);
        }
    }

    const float4 bias = *(const float4*)&bu[c0 + tx*4];
    #pragma unroll
    for (int ry = 0; ry < 8; ry++) {
        float4 o;
        o.x = acc[ry][0] + bias.x;
        o.y = acc[ry][1] + bias.y;
        o.z = acc[ry][2] + bias.z;
        o.w = acc[ry][3] + bias.w;
        *(float4*)&out[(size_t)(r0 + ty*8 + ry)*Ev + c0 + tx*4] = o;
    }
}

// ---------------------------------------------------------------------------
extern "C" void kernel_launch(void* const* d_in, const int* in_sizes, int n_in,
                              void* d_out, int out_size)
{
    const float* x   = (const float*)d_in[0];
    const float* rk  = (const float*)d_in[1];
    const float* rv  = (const float*)d_in[2];
    const int*   msk = (const int*)  d_in[3];
    const float* Wq  = (const float*)d_in[4];
    const float* Wk  = (const float*)d_in[5];
    const float* Wv  = (const float*)d_in[6];
    const float* Wu  = (const float*)d_in[7];
    const float* bu  = (const float*)d_in[8];
    float* out = (float*)d_out;

    qkv_kernel<<<Bv*Tv, 256>>>(x, Wq, Wk, Wv);
    scc_kernel<<<dim3(4, 4, Bv*Hv), 256>>>();
    attn_kernel<<<Bv*Tv, 256>>>(rk, rv, msk);
    proj_kernel<<<dim3(16, 16), 64>>>(Wu, bu, out);
}

// round 4
// speedup vs baseline: 1.1603x; 1.1573x over previous
#include <cuda_runtime.h>

#define Bv 4
#define Tv 256
#define Ev 512
#define Hv 8
#define Sv 64

// scratch (allocation-free rule: __device__ globals)
__device__ float g_q[Bv*Tv*Ev];
__device__ float g_k[Bv*Tv*Ev];
__device__ float g_v[Bv*Tv*Ev];
__device__ float g_scc[Bv*Hv*Tv*Tv];   // [b][n][i][j]
__device__ float g_vec[Bv*Tv*Ev];

// ---------------------------------------------------------------------------
// K1: per-token q/k/v projections.  q[b,t,n,o] = sum_d x[b,t,n*64+d]*W[o,d]
// ---------------------------------------------------------------------------
__global__ void __launch_bounds__(256) qkv_kernel(const float* __restrict__ x,
                                                  const float* __restrict__ Wq,
                                                  const float* __restrict__ Wk,
                                                  const float* __restrict__ Wv)
{
    __shared__ float Ws[64][65];
    __shared__ float xs[Ev];
    const int bt  = blockIdx.x;
    const int tid = threadIdx.x;

    xs[tid]       = x[(size_t)bt*Ev + tid];
    xs[tid + 256] = x[(size_t)bt*Ev + tid + 256];

    const float* Wlist[3] = {Wq, Wk, Wv};
    float*       Olist[3] = {g_q, g_k, g_v};

    #pragma unroll
    for (int w = 0; w < 3; w++) {
        __syncthreads();
        const float* W = Wlist[w];
        for (int idx = tid; idx < 64*64; idx += 256)
            Ws[idx >> 6][idx & 63] = W[idx];
        __syncthreads();

        const int e0 = 2 * tid;
        const int n  = e0 >> 6;
        const int o0 = e0 & 63;
        const float* xr = &xs[n * 64];
        float a0 = 0.f, a1 = 0.f;
        #pragma unroll
        for (int d = 0; d < 64; d++) {
            const float xv = xr[d];
            a0 = fmaf(xv, Ws[o0][d],     a0);
            a1 = fmaf(xv, Ws[o0 + 1][d], a1);
        }
        Olist[w][(size_t)bt*Ev + e0]     = a0;
        Olist[w][(size_t)bt*Ev + e0 + 1] = a1;
    }
}

// ---------------------------------------------------------------------------
// K2: content-content scores  scc[b][n][i][j] = sum_d q[b,i,n,d]*k[b,j,n,d]
// ---------------------------------------------------------------------------
__global__ void __launch_bounds__(256) scc_kernel()
{
    __shared__ float qs[64][65];
    __shared__ float ks[64][65];
    const int it = blockIdx.x * 64;
    const int jt = blockIdx.y * 64;
    const int b  = blockIdx.z >> 3;
    const int n  = blockIdx.z & 7;
    const int tid = threadIdx.x;

    for (int idx = tid; idx < 4096; idx += 256) {
        const int r = idx >> 6, d = idx & 63;
        qs[r][d] = g_q[(((size_t)b*Tv + it + r)*Hv + n)*Sv + d];
        ks[r][d] = g_k[(((size_t)b*Tv + jt + r)*Hv + n)*Sv + d];
    }
    __syncthreads();

    const int ty = tid >> 4, tx = tid & 15;
    float acc[4][4] = {};
    #pragma unroll 8
    for (int d = 0; d < 64; d++) {
        float a[4], c[4];
        #pragma unroll
        for (int r = 0; r < 4; r++) a[r] = qs[ty*4 + r][d];
        #pragma unroll
        for (int cc = 0; cc < 4; cc++) c[cc] = ks[tx*4 + cc][d];
        #pragma unroll
        for (int r = 0; r < 4; r++)
            #pragma unroll
            for (int cc = 0; cc < 4; cc++)
                acc[r][cc] = fmaf(a[r], c[cc], acc[r][cc]);
    }

    #pragma unroll
    for (int r = 0; r < 4; r++)
        #pragma unroll
        for (int cc = 0; cc < 4; cc++)
            g_scc[(((size_t)b*Hv + n)*Tv + it + ty*4 + r)*Tv + jt + tx*4 + cc] = acc[r][cc];
}

// ---------------------------------------------------------------------------
// K3: streaming attention (R1 structure: float2, 8-deep MLP, warp per head).
// ---------------------------------------------------------------------------
__global__ void __launch_bounds__(256) attn_kernel(const float* __restrict__ ek,
                                                   const float* __restrict__ ev,
                                                   const int*   __restrict__ mask)
{
    __shared__ float sc[Hv][Tv];     // scores -> probs
    __shared__ float qsm[Ev];

    const int bi   = blockIdx.x;
    const int b    = bi >> 8;
    const int i    = bi & 255;
    const int tid  = threadIdx.x;
    const int warp = tid >> 5;
    const int lane = tid & 31;

    qsm[tid]       = g_q[(size_t)bi*Ev + tid];
    qsm[tid + 256] = g_q[(size_t)bi*Ev + tid + 256];

    // preload content-content scores: sc[n][j]
    #pragma unroll
    for (int t = 0; t < 8; t++)
        sc[t][tid] = g_scc[(((size_t)b*Hv + t)*Tv + i)*Tv + tid];
    __syncthreads();

    const float q0 = qsm[warp*64 + 2*lane];
    const float q1 = qsm[warp*64 + 2*lane + 1];

    const float2* ekp = (const float2*)ek + (((size_t)bi*Tv*Ev) >> 1) + warp*32 + lane;

    // ---- Pass A: stream ek, add q.ek to scores ----
    for (int j0 = 0; j0 < Tv; j0 += 8) {
        float2 r[8];
        #pragma unroll
        for (int u = 0; u < 8; u++) r[u] = ekp[(size_t)(j0 + u) * 256];
        #pragma unroll
        for (int u = 0; u < 8; u++) {
            float p = fmaf(r[u].x, q0, r[u].y * q1);
            p += __shfl_xor_sync(0xffffffffu, p, 16);
            p += __shfl_xor_sync(0xffffffffu, p, 8);
            p += __shfl_xor_sync(0xffffffffu, p, 4);
            p += __shfl_xor_sync(0xffffffffu, p, 2);
            p += __shfl_xor_sync(0xffffffffu, p, 1);
            if (lane == 0) sc[warp][j0 + u] += p;
        }
    }
    __syncwarp();

    // ---- softmax per head (warp-local over 256 j) ----
    const float scale = 0.125f;   // 1/sqrt(64)
    const int* mrow = mask + (size_t)bi * Tv;
    float vbuf[8];
    float mx = -1e30f;
    #pragma unroll
    for (int t = 0; t < 8; t++) {
        const int j = lane + 32*t;
        float s = sc[warp][j];
        s = (mrow[j] == 0) ? -1e9f : s * scale;
        vbuf[t] = s;
        mx = fmaxf(mx, s);
    }
    mx = fmaxf(mx, __shfl_xor_sync(0xffffffffu, mx, 16));
    mx = fmaxf(mx, __shfl_xor_sync(0xffffffffu, mx, 8));
    mx = fmaxf(mx, __shfl_xor_sync(0xffffffffu, mx, 4));
    mx = fmaxf(mx, __shfl_xor_sync(0xffffffffu, mx, 2));
    mx = fmaxf(mx, __shfl_xor_sync(0xffffffffu, mx, 1));
    float sum = 0.f;
    #pragma unroll
    for (int t = 0; t < 8; t++) {
        const float e = expf(vbuf[t] - mx);
        vbuf[t] = e;
        sum += e;
    }
    sum += __shfl_xor_sync(0xffffffffu, sum, 16);
    sum += __shfl_xor_sync(0xffffffffu, sum, 8);
    sum += __shfl_xor_sync(0xffffffffu, sum, 4);
    sum += __shfl_xor_sync(0xffffffffu, sum, 2);
    sum += __shfl_xor_sync(0xffffffffu, sum, 1);
    const float inv = 1.f / sum;
    #pragma unroll
    for (int t = 0; t < 8; t++)
        sc[warp][lane + 32*t] = vbuf[t] * inv;
    __syncwarp();

    // ---- Pass B: stream ev + L2-hit v, accumulate weighted sum ----
    const float2* evp = (const float2*)ev  + (((size_t)bi*Tv*Ev) >> 1) + warp*32 + lane;
    const float2* vp  = (const float2*)g_v + (((size_t)b *Tv*Ev) >> 1) + warp*32 + lane;
    float a0 = 0.f, a1 = 0.f;
    for (int j0 = 0; j0 < Tv; j0 += 8) {
        float2 re[8], rv[8];
        #pragma unroll
        for (int u = 0; u < 8; u++) re[u] = evp[(size_t)(j0 + u) * 256];
        #pragma unroll
        for (int u = 0; u < 8; u++) rv[u] = vp[(size_t)(j0 + u) * 256];
        #pragma unroll
        for (int u = 0; u < 8; u++) {
            const float p = sc[warp][j0 + u];
            a0 = fmaf(p, re[u].x + rv[u].x, a0);
            a1 = fmaf(p, re[u].y + rv[u].y, a1);
        }
    }
    g_vec[(size_t)bi*Ev + warp*64 + 2*lane]     = a0;
    g_vec[(size_t)bi*Ev + warp*64 + 2*lane + 1] = a1;
}

// ---------------------------------------------------------------------------
// K4: out = vec @ Wu^T + bu.  BM=64, BN=32, BK=32, 128 threads, TM=4 x TN=4.
// grid = (16,16) = 256 CTAs; ~2 CTAs/SM (8 warps) to hide latency.
// ---------------------------------------------------------------------------
__global__ void __launch_bounds__(128) proj_kernel(const float* __restrict__ Wu,
                                                   const float* __restrict__ bu,
                                                   float* __restrict__ out)
{
    __shared__ float As[32][68];   // [k][r]  r0..r0+63
    __shared__ float Bs[32][36];   // [k][c]  c0..c0+31
    const int r0  = blockIdx.x * 64;
    const int c0  = blockIdx.y * 32;
    const int tid = threadIdx.x;
    const int ty  = tid >> 3;       // 0..15 -> rows ty*4..ty*4+3
    const int tx  = tid & 7;        // 0..7  -> cols tx*4..tx*4+3

    float acc[4][4] = {};

    for (int k0 = 0; k0 < Ev; k0 += 32) {
        __syncthreads();
        // As: 64 rows x 32 k = 512 float4 chunks, 4 per thread
        #pragma unroll
        for (int ch = tid; ch < 512; ch += 128) {
            const int r = ch >> 3, k = (ch & 7) * 4;
            const float4 v4 = *(const float4*)&g_vec[(size_t)(r0 + r)*Ev + k0 + k];
            As[k][r] = v4.x; As[k+1][r] = v4.y; As[k+2][r] = v4.z; As[k+3][r] = v4.w;
        }
        // Bs: 32 rows x 32 k = 256 float4 chunks, 2 per thread
        #pragma unroll
        for (int ch = tid; ch < 256; ch += 128) {
            const int c = ch >> 3, k = (ch & 7) * 4;
            const float4 v4 = *(const float4*)&Wu[(size_t)(c0 + c)*Ev + k0 + k];
            Bs[k][c] = v4.x; Bs[k+1][c] = v4.y; Bs[k+2][c] = v4.z; Bs[k+3][c] = v4.w;
        }
        __syncthreads();

        #pragma unroll 8
        for (int k = 0; k < 32; k++) {
            const float4 a4 = *(const float4*)&As[k][ty*4];
            const float4 b4 = *(const float4*)&Bs[k][tx*4];
            const float a[4] = {a4.x, a4.y, a4.z, a4.w};
            const float c[4] = {b4.x, b4.y, b4.z, b4.w};
            #pragma unroll
            for (int ry = 0; ry < 4; ry++)
                #pragma unroll
                for (int cx = 0; cx < 4; cx++)
                    acc[ry][cx] = fmaf(a[ry], c[cx], acc[ry][cx]);
        }
    }

    const float4 bias = *(const float4*)&bu[c0 + tx*4];
    #pragma unroll
    for (int ry = 0; ry < 4; ry++) {
        float4 o;
        o.x = acc[ry][0] + bias.x;
        o.y = acc[ry][1] + bias.y;
        o.z = acc[ry][2] + bias.z;
        o.w = acc[ry][3] + bias.w;
        *(float4*)&out[(size_t)(r0 + ty*4 + ry)*Ev + c0 + tx*4] = o;
    }
}

// ---------------------------------------------------------------------------
extern "C" void kernel_launch(void* const* d_in, const int* in_sizes, int n_in,
                              void* d_out, int out_size)
{
    const float* x   = (const float*)d_in[0];
    const float* rk  = (const float*)d_in[1];
    const float* rv  = (const float*)d_in[2];
    const int*   msk = (const int*)  d_in[3];
    const float* Wq  = (const float*)d_in[4];
    const float* Wk  = (const float*)d_in[5];
    const float* Wv  = (const float*)d_in[6];
    const float* Wu  = (const float*)d_in[7];
    const float* bu  = (const float*)d_in[8];
    float* out = (float*)d_out;

    qkv_kernel<<<Bv*Tv, 256>>>(x, Wq, Wk, Wv);
    scc_kernel<<<dim3(4, 4, Bv*Hv), 256>>>();
    attn_kernel<<<Bv*Tv, 256>>>(rk, rv, msk);
    proj_kernel<<<dim3(16, 16), 128>>>(Wu, bu, out);
}